// round 1
// baseline (speedup 1.0000x reference)
#include <cuda_runtime.h>
#include <math.h>

#define NE 8
#define NH 1024
#define NI 2048
#define NT 2048

#define BM 64
#define BN 64
#define BK 32

// Scratch (static __device__ — allocation-free per harness rules)
__device__ int   g_count[NE];
__device__ int   g_list[NE * NT];
__device__ float g_wt[NE * NT];
__device__ float g_act[(size_t)NE * NT * NI];   // [e][slot][i]

__global__ void zero_counts_kernel() {
    if (threadIdx.x < NE) g_count[threadIdx.x] = 0;
}

// One warp per token: logits, top-2, renormalized weights, scatter into expert lists.
__global__ void router_kernel(const float* __restrict__ x, const float* __restrict__ gw) {
    int warp = (blockIdx.x * blockDim.x + threadIdx.x) >> 5;
    int lane = threadIdx.x & 31;
    if (warp >= NT) return;
    const float* xr = x + (size_t)warp * NH;
    float logits[NE];
#pragma unroll
    for (int e = 0; e < NE; e++) {
        float p = 0.f;
        for (int h = lane; h < NH; h += 32) p += xr[h] * gw[e * NH + h];
#pragma unroll
        for (int o = 16; o > 0; o >>= 1) p += __shfl_xor_sync(0xffffffffu, p, o);
        logits[e] = p;
    }
    if (lane == 0) {
        int i1 = 0;
#pragma unroll
        for (int e = 1; e < NE; e++) if (logits[e] > logits[i1]) i1 = e;
        int i2 = (i1 == 0) ? 1 : 0;
#pragma unroll
        for (int e = 0; e < NE; e++) if (e != i1 && logits[e] > logits[i2]) i2 = e;
        // renormalized top-2 softmax weights: e^{l1}/(e^{l1}+e^{l2}), ...
        float m  = logits[i1];
        float s2 = expf(logits[i2] - m);
        float inv = 1.f / (1.f + s2);
        int p0 = atomicAdd(&g_count[i1], 1);
        g_list[i1 * NT + p0] = warp;
        g_wt [i1 * NT + p0] = inv;
        int p1 = atomicAdd(&g_count[i2], 1);
        g_list[i2 * NT + p1] = warp;
        g_wt [i2 * NT + p1] = s2 * inv;
    }
}

// Fused g = x*w1^T, u = x*w3^T, act = silu(g)*u for tokens routed to expert e.
__global__ __launch_bounds__(256) void gemm1_kernel(const float* __restrict__ x,
                                                    const float* __restrict__ w1,
                                                    const float* __restrict__ w3) {
    int e   = blockIdx.z;
    int n_e = g_count[e];
    int row0 = blockIdx.y * BM;         // slot within expert
    if (row0 >= n_e) return;
    int col0 = blockIdx.x * BN;         // i

    __shared__ float As [BM][BK + 1];
    __shared__ float B1s[BN][BK + 1];
    __shared__ float B3s[BN][BK + 1];
    __shared__ int   toks[BM];

    int tid = threadIdx.x;
    int tx = tid & 15, ty = tid >> 4;

    if (tid < BM) {
        int slot = row0 + tid;
        toks[tid] = (slot < n_e) ? g_list[e * NT + slot] : -1;
    }
    __syncthreads();

    const float* w1e = w1 + (size_t)e * NI * NH;
    const float* w3e = w3 + (size_t)e * NI * NH;

    float ag[4][4] = {}, au[4][4] = {};

    for (int k0 = 0; k0 < NH; k0 += BK) {
#pragma unroll
        for (int l = tid; l < BM * BK / 4; l += 256) {
            int r = l >> 3;
            int c = (l & 7) << 2;
            int t = toks[r];
            float4 v = make_float4(0.f, 0.f, 0.f, 0.f);
            if (t >= 0) v = *(const float4*)(x + (size_t)t * NH + k0 + c);
            As[r][c] = v.x; As[r][c + 1] = v.y; As[r][c + 2] = v.z; As[r][c + 3] = v.w;
        }
#pragma unroll
        for (int l = tid; l < BN * BK / 4; l += 256) {
            int r = l >> 3;
            int c = (l & 7) << 2;
            size_t off = (size_t)(col0 + r) * NH + k0 + c;
            float4 v1 = *(const float4*)(w1e + off);
            float4 v3 = *(const float4*)(w3e + off);
            B1s[r][c] = v1.x; B1s[r][c + 1] = v1.y; B1s[r][c + 2] = v1.z; B1s[r][c + 3] = v1.w;
            B3s[r][c] = v3.x; B3s[r][c + 1] = v3.y; B3s[r][c + 2] = v3.z; B3s[r][c + 3] = v3.w;
        }
        __syncthreads();
#pragma unroll
        for (int kk = 0; kk < BK; kk++) {
            float a[4], b1[4], b3[4];
#pragma unroll
            for (int m = 0; m < 4; m++) a[m] = As[ty * 4 + m][kk];
#pragma unroll
            for (int n = 0; n < 4; n++) { b1[n] = B1s[tx * 4 + n][kk]; b3[n] = B3s[tx * 4 + n][kk]; }
#pragma unroll
            for (int m = 0; m < 4; m++)
#pragma unroll
                for (int n = 0; n < 4; n++) {
                    ag[m][n] += a[m] * b1[n];
                    au[m][n] += a[m] * b3[n];
                }
        }
        __syncthreads();
    }

#pragma unroll
    for (int m = 0; m < 4; m++) {
        int slot = row0 + ty * 4 + m;
        if (slot < n_e) {
            float* dst = g_act + ((size_t)(e * NT + slot)) * NI + col0 + tx * 4;
#pragma unroll
            for (int n = 0; n < 4; n++) {
                float g = ag[m][n];
                float s = g / (1.f + expf(-g));   // silu
                dst[n] = s * au[m][n];
            }
        }
    }
}

// y = act * w2^T, accumulated into out with routing weight (atomicAdd; exactly 2 adds/elem).
__global__ __launch_bounds__(256) void gemm2_kernel(const float* __restrict__ w2,
                                                    float* __restrict__ out) {
    int e   = blockIdx.z;
    int n_e = g_count[e];
    int row0 = blockIdx.y * BM;         // slot
    if (row0 >= n_e) return;
    int col0 = blockIdx.x * BN;         // h

    __shared__ float As[BM][BK + 1];
    __shared__ float Bs[BN][BK + 1];
    __shared__ int   toks[BM];
    __shared__ float wts[BM];

    int tid = threadIdx.x;
    int tx = tid & 15, ty = tid >> 4;

    if (tid < BM) {
        int slot = row0 + tid;
        toks[tid] = (slot < n_e) ? g_list[e * NT + slot] : -1;
        wts[tid]  = (slot < n_e) ? g_wt [e * NT + slot] : 0.f;
    }
    __syncthreads();

    const float* w2e  = w2 + (size_t)e * NH * NI;
    const float* acte = g_act + (size_t)e * NT * NI;

    float acc[4][4] = {};

    for (int k0 = 0; k0 < NI; k0 += BK) {
#pragma unroll
        for (int l = tid; l < BM * BK / 4; l += 256) {
            int r = l >> 3;
            int c = (l & 7) << 2;
            int slot = row0 + r;
            float4 v = make_float4(0.f, 0.f, 0.f, 0.f);
            if (slot < n_e) v = *(const float4*)(acte + (size_t)slot * NI + k0 + c);
            As[r][c] = v.x; As[r][c + 1] = v.y; As[r][c + 2] = v.z; As[r][c + 3] = v.w;
        }
#pragma unroll
        for (int l = tid; l < BN * BK / 4; l += 256) {
            int r = l >> 3;
            int c = (l & 7) << 2;
            float4 v = *(const float4*)(w2e + (size_t)(col0 + r) * NI + k0 + c);
            Bs[r][c] = v.x; Bs[r][c + 1] = v.y; Bs[r][c + 2] = v.z; Bs[r][c + 3] = v.w;
        }
        __syncthreads();
#pragma unroll
        for (int kk = 0; kk < BK; kk++) {
            float a[4], b[4];
#pragma unroll
            for (int m = 0; m < 4; m++) a[m] = As[ty * 4 + m][kk];
#pragma unroll
            for (int n = 0; n < 4; n++) b[n] = Bs[tx * 4 + n][kk];
#pragma unroll
            for (int m = 0; m < 4; m++)
#pragma unroll
                for (int n = 0; n < 4; n++) acc[m][n] += a[m] * b[n];
        }
        __syncthreads();
    }

#pragma unroll
    for (int m = 0; m < 4; m++) {
        int slot = row0 + ty * 4 + m;
        if (slot < n_e) {
            int   t = toks[ty * 4 + m];
            float w = wts [ty * 4 + m];
            float* dst = out + (size_t)t * NH + col0 + tx * 4;
#pragma unroll
            for (int n = 0; n < 4; n++) atomicAdd(&dst[n], w * acc[m][n]);
        }
    }
}

extern "C" void kernel_launch(void* const* d_in, const int* in_sizes, int n_in,
                              void* d_out, int out_size) {
    const float* x  = (const float*)d_in[0];   // hidden_states [1,2048,1024]
    const float* gw = (const float*)d_in[1];   // gate_w [8,1024]
    const float* w1 = (const float*)d_in[2];   // [8,2048,1024]
    const float* w3 = (const float*)d_in[3];   // [8,2048,1024]
    const float* w2 = (const float*)d_in[4];   // [8,1024,2048]
    float* out = (float*)d_out;                // [1,2048,1024]

    cudaMemsetAsync(out, 0, (size_t)out_size * sizeof(float), 0);
    zero_counts_kernel<<<1, 32>>>();
    router_kernel<<<(NT * 32 + 255) / 256, 256>>>(x, gw);

    dim3 grid1(NI / BN, (NT + BM - 1) / BM, NE);
    gemm1_kernel<<<grid1, 256>>>(x, w1, w3);

    dim3 grid2(NH / BN, (NT + BM - 1) / BM, NE);
    gemm2_kernel<<<grid2, 256>>>(w2, out);
}

// round 3
// speedup vs baseline: 2.5569x; 2.5569x over previous
#include <cuda_runtime.h>
#include <cuda_bf16.h>
#include <math.h>
#include <stdint.h>

#define NE 8
#define NH 1024
#define NI 2048
#define NT 2048
#define RS 80   // smem row stride (bytes): 20-word stride -> conflict-free ldmatrix

// Scratch (static __device__ — allocation-free per harness rules)
__device__ int   g_count[NE];
__device__ int   g_list[NE * NT];
__device__ float g_wt[NE * NT];
__device__ __nv_bfloat16 g_act_hi[(size_t)NE * NT * NI];
__device__ __nv_bfloat16 g_act_lo[(size_t)NE * NT * NI];

// ---------------- helpers ----------------
__device__ __forceinline__ uint32_t smem_u32(const void* p) {
    uint32_t r;
    asm("{ .reg .u64 t; cvta.to.shared.u64 t, %1; cvt.u32.u64 %0, t; }" : "=r"(r) : "l"(p));
    return r;
}
__device__ __forceinline__ void ldm_x4(uint32_t a, uint32_t r[4]) {
    asm volatile("ldmatrix.sync.aligned.m8n8.x4.shared.b16 {%0,%1,%2,%3}, [%4];"
                 : "=r"(r[0]), "=r"(r[1]), "=r"(r[2]), "=r"(r[3]) : "r"(a));
}
__device__ __forceinline__ void mma16816(float d[4], const uint32_t a[4],
                                         uint32_t b0, uint32_t b1) {
    asm volatile("mma.sync.aligned.m16n8k16.row.col.f32.bf16.bf16.f32 "
                 "{%0,%1,%2,%3}, {%4,%5,%6,%7}, {%8,%9}, {%0,%1,%2,%3};"
                 : "+f"(d[0]), "+f"(d[1]), "+f"(d[2]), "+f"(d[3])
                 : "r"(a[0]), "r"(a[1]), "r"(a[2]), "r"(a[3]), "r"(b0), "r"(b1));
}
__device__ __forceinline__ void sts64(uint32_t a, uint32_t x, uint32_t y) {
    asm volatile("st.shared.v2.b32 [%0], {%1,%2};" :: "r"(a), "r"(x), "r"(y) : "memory");
}
__device__ __forceinline__ void sts128(uint32_t a, uint4 v) {
    asm volatile("st.shared.v4.b32 [%0], {%1,%2,%3,%4};"
                 :: "r"(a), "r"(v.x), "r"(v.y), "r"(v.z), "r"(v.w) : "memory");
}
__device__ __forceinline__ uint32_t pk2(float a, float b) {
    __nv_bfloat162 t = __floats2bfloat162_rn(a, b);
    return *reinterpret_cast<uint32_t*>(&t);
}
__device__ __forceinline__ void split4(float4 v, uint32_t& h0, uint32_t& h1,
                                       uint32_t& l0, uint32_t& l1) {
    float hx = __bfloat162float(__float2bfloat16_rn(v.x));
    float hy = __bfloat162float(__float2bfloat16_rn(v.y));
    float hz = __bfloat162float(__float2bfloat16_rn(v.z));
    float hw = __bfloat162float(__float2bfloat16_rn(v.w));
    h0 = pk2(hx, hy); h1 = pk2(hz, hw);
    l0 = pk2(v.x - hx, v.y - hy); l1 = pk2(v.z - hz, v.w - hw);
}

// ---------------- router ----------------
__global__ void zero_counts_kernel() {
    if (threadIdx.x < NE) g_count[threadIdx.x] = 0;
}

__global__ __launch_bounds__(256) void router_kernel(const float* __restrict__ x,
                                                     const float* __restrict__ gw) {
    int warp = (blockIdx.x * blockDim.x + threadIdx.x) >> 5;
    int lane = threadIdx.x & 31;
    if (warp >= NT) return;
    const float* xr = x + (size_t)warp * NH;
    float xv[32];
#pragma unroll
    for (int j = 0; j < 32; j++) xv[j] = xr[j * 32 + lane];
    float logits[NE];
#pragma unroll
    for (int e = 0; e < NE; e++) {
        const float* g = gw + e * NH;
        float p = 0.f;
#pragma unroll
        for (int j = 0; j < 32; j++) p += xv[j] * g[j * 32 + lane];
#pragma unroll
        for (int o = 16; o > 0; o >>= 1) p += __shfl_xor_sync(0xffffffffu, p, o);
        logits[e] = p;
    }
    if (lane == 0) {
        int i1 = 0;
#pragma unroll
        for (int e = 1; e < NE; e++) if (logits[e] > logits[i1]) i1 = e;
        int i2 = (i1 == 0) ? 1 : 0;
#pragma unroll
        for (int e = 0; e < NE; e++) if (e != i1 && logits[e] > logits[i2]) i2 = e;
        float s2  = __expf(logits[i2] - logits[i1]);
        float inv = 1.f / (1.f + s2);
        int p0 = atomicAdd(&g_count[i1], 1);
        g_list[i1 * NT + p0] = warp;
        g_wt [i1 * NT + p0] = inv;
        int p1 = atomicAdd(&g_count[i2], 1);
        g_list[i2 * NT + p1] = warp;
        g_wt [i2 * NT + p1] = s2 * inv;
    }
}

// ---------------- GEMM1: act = silu(x*w1^T) * (x*w3^T) ----------------
// CTA tile 128(M slots) x 64(N=i), K-chunk 32. 8 warps: warp tile 64x16.
__global__ __launch_bounds__(256) void gemm1_mma(const float* __restrict__ x,
                                                 const float* __restrict__ w1,
                                                 const float* __restrict__ w3) {
    int e   = blockIdx.z;
    int n_e = g_count[e];
    int row0 = blockIdx.y * 128;
    if (row0 >= n_e) return;
    int col0 = blockIdx.x * 64;

    __shared__ __align__(128) char sm[1024 + 2 * 128 * RS + 4 * 64 * RS]; // 42496
    int* toks = (int*)sm;
    int tid = threadIdx.x, wid = tid >> 5, lane = tid & 31;
    if (tid < 128) toks[tid] = (row0 + tid < n_e) ? g_list[e * NT + row0 + tid] : -1;
    __syncthreads();

    uint32_t smb = smem_u32(sm);
    const uint32_t AH = 1024, AL = AH + 128 * RS;
    const uint32_t B1H = AL + 128 * RS, B1L = B1H + 64 * RS;
    const uint32_t B3H = B1L + 64 * RS, B3L = B3H + 64 * RS;

    // global prefetch pointers
    const float* ap[4]; bool avld[4]; uint32_t sa[4];
#pragma unroll
    for (int j = 0; j < 4; j++) {
        int idx = j * 256 + tid, r = idx >> 3, c4 = idx & 7;
        int t = toks[r];
        avld[j] = t >= 0;
        ap[j] = x + (size_t)(t < 0 ? 0 : t) * NH + c4 * 4;
        sa[j] = (uint32_t)(r * RS + c4 * 8);
    }
    const float *bp1[2], *bp3[2]; uint32_t sb[2];
#pragma unroll
    for (int j = 0; j < 2; j++) {
        int idx = j * 256 + tid, r = idx >> 3, c4 = idx & 7;
        size_t off = (size_t)e * NI * NH + (size_t)(col0 + r) * NH + c4 * 4;
        bp1[j] = w1 + off;
        bp3[j] = w3 + off;
        sb[j] = (uint32_t)(r * RS + c4 * 8);
    }

    // ldmatrix lane offsets
    int m0 = (wid & 1) * 64, n0 = (wid >> 1) * 16;
    uint32_t a_off = (uint32_t)((m0 + (lane & 15)) * RS + ((lane >> 4) << 4));
    uint32_t b_off = (uint32_t)((n0 + (lane & 7) + ((lane >> 4) << 3)) * RS +
                                (((lane >> 3) & 1) << 4));

    float dg[4][2][4] = {}, du[4][2][4] = {};

    float4 av[4], b1v[2], b3v[2];
#pragma unroll
    for (int j = 0; j < 4; j++)
        av[j] = avld[j] ? __ldg((const float4*)ap[j]) : make_float4(0.f, 0.f, 0.f, 0.f);
#pragma unroll
    for (int j = 0; j < 2; j++) { b1v[j] = __ldg((const float4*)bp1[j]); b3v[j] = __ldg((const float4*)bp3[j]); }

#pragma unroll 1
    for (int c = 0; c < NH / 32; c++) {
        __syncthreads();
        uint32_t h0, h1, l0, l1;
#pragma unroll
        for (int j = 0; j < 4; j++) {
            split4(av[j], h0, h1, l0, l1);
            sts64(smb + AH + sa[j], h0, h1);
            sts64(smb + AL + sa[j], l0, l1);
        }
#pragma unroll
        for (int j = 0; j < 2; j++) {
            split4(b1v[j], h0, h1, l0, l1);
            sts64(smb + B1H + sb[j], h0, h1);
            sts64(smb + B1L + sb[j], l0, l1);
            split4(b3v[j], h0, h1, l0, l1);
            sts64(smb + B3H + sb[j], h0, h1);
            sts64(smb + B3L + sb[j], l0, l1);
        }
        __syncthreads();
        if (c + 1 < NH / 32) {
#pragma unroll
            for (int j = 0; j < 4; j++) {
                ap[j] += 32;
                av[j] = avld[j] ? __ldg((const float4*)ap[j]) : make_float4(0.f, 0.f, 0.f, 0.f);
            }
#pragma unroll
            for (int j = 0; j < 2; j++) {
                bp1[j] += 32; bp3[j] += 32;
                b1v[j] = __ldg((const float4*)bp1[j]);
                b3v[j] = __ldg((const float4*)bp3[j]);
            }
        }
#pragma unroll
        for (int s = 0; s < 2; s++) {
            uint32_t Ah[4][4], Al[4][4];
#pragma unroll
            for (int mt = 0; mt < 4; mt++) {
                ldm_x4(smb + AH + a_off + mt * 16 * RS + s * 32, Ah[mt]);
                ldm_x4(smb + AL + a_off + mt * 16 * RS + s * 32, Al[mt]);
            }
            uint32_t q1h[4], q1l[4], q3h[4], q3l[4];
            ldm_x4(smb + B1H + b_off + s * 32, q1h);
            ldm_x4(smb + B1L + b_off + s * 32, q1l);
            ldm_x4(smb + B3H + b_off + s * 32, q3h);
            ldm_x4(smb + B3L + b_off + s * 32, q3l);
#pragma unroll
            for (int mt = 0; mt < 4; mt++)
#pragma unroll
                for (int nt = 0; nt < 2; nt++) {
                    mma16816(dg[mt][nt], Ah[mt], q1h[nt * 2], q1h[nt * 2 + 1]);
                    mma16816(dg[mt][nt], Ah[mt], q1l[nt * 2], q1l[nt * 2 + 1]);
                    mma16816(dg[mt][nt], Al[mt], q1h[nt * 2], q1h[nt * 2 + 1]);
                    mma16816(du[mt][nt], Ah[mt], q3h[nt * 2], q3h[nt * 2 + 1]);
                    mma16816(du[mt][nt], Ah[mt], q3l[nt * 2], q3l[nt * 2 + 1]);
                    mma16816(du[mt][nt], Al[mt], q3h[nt * 2], q3h[nt * 2 + 1]);
                }
        }
    }

    // epilogue: silu(g)*u, split to bf16 hi/lo, store
    int lr = lane >> 2, lc = lane & 3;
#pragma unroll
    for (int mt = 0; mt < 4; mt++)
#pragma unroll
        for (int p = 0; p < 2; p++) {
            int m = m0 + mt * 16 + lr + p * 8;
            int slot = row0 + m;
            if (slot < n_e) {
#pragma unroll
                for (int nt = 0; nt < 2; nt++) {
                    int n = col0 + n0 + nt * 8 + lc * 2;
                    float g0 = dg[mt][nt][2 * p], g1 = dg[mt][nt][2 * p + 1];
                    float u0 = du[mt][nt][2 * p], u1 = du[mt][nt][2 * p + 1];
                    float a0 = u0 * g0 / (1.f + __expf(-g0));
                    float a1 = u1 * g1 / (1.f + __expf(-g1));
                    __nv_bfloat16 h0 = __float2bfloat16_rn(a0);
                    __nv_bfloat16 h1 = __float2bfloat16_rn(a1);
                    __nv_bfloat162 hp; hp.x = h0; hp.y = h1;
                    size_t o = ((size_t)e * NT + slot) * NI + n;
                    *(uint32_t*)(g_act_hi + o) = *reinterpret_cast<uint32_t*>(&hp);
                    *(uint32_t*)(g_act_lo + o) =
                        pk2(a0 - __bfloat162float(h0), a1 - __bfloat162float(h1));
                }
            }
        }
}

// ---------------- GEMM2: out += route_w * (act * w2^T) ----------------
__global__ __launch_bounds__(256) void gemm2_mma(const float* __restrict__ w2,
                                                 float* __restrict__ out) {
    int e   = blockIdx.z;
    int n_e = g_count[e];
    int row0 = blockIdx.y * 128;
    if (row0 >= n_e) return;
    int col0 = blockIdx.x * 64;

    __shared__ __align__(128) char sm[1024 + 2 * 128 * RS + 2 * 64 * RS]; // 31744
    int*   toks = (int*)sm;
    float* wts  = (float*)(sm + 512);
    int tid = threadIdx.x, wid = tid >> 5, lane = tid & 31;
    if (tid < 128) {
        int slot = row0 + tid;
        toks[tid] = (slot < n_e) ? g_list[e * NT + slot] : 0;
        wts[tid]  = (slot < n_e) ? g_wt [e * NT + slot] : 0.f;
    }
    __syncthreads();

    uint32_t smb = smem_u32(sm);
    const uint32_t AH = 1024, AL = AH + 128 * RS;
    const uint32_t BH = AL + 128 * RS, BL = BH + 64 * RS;

    const __nv_bfloat16 *aph[2], *apl[2]; uint32_t sa[2];
#pragma unroll
    for (int j = 0; j < 2; j++) {
        int idx = j * 256 + tid, r = idx >> 2, c16 = idx & 3;
        size_t off = ((size_t)e * NT + row0 + r) * NI + c16 * 8;
        aph[j] = g_act_hi + off;
        apl[j] = g_act_lo + off;
        sa[j] = (uint32_t)(r * RS + c16 * 16);
    }
    const float* bp[2]; uint32_t sb[2];
#pragma unroll
    for (int j = 0; j < 2; j++) {
        int idx = j * 256 + tid, r = idx >> 3, c4 = idx & 7;
        bp[j] = w2 + (size_t)e * NH * NI + (size_t)(col0 + r) * NI + c4 * 4;
        sb[j] = (uint32_t)(r * RS + c4 * 8);
    }

    int m0 = (wid & 1) * 64, n0 = (wid >> 1) * 16;
    uint32_t a_off = (uint32_t)((m0 + (lane & 15)) * RS + ((lane >> 4) << 4));
    uint32_t b_off = (uint32_t)((n0 + (lane & 7) + ((lane >> 4) << 3)) * RS +
                                (((lane >> 3) & 1) << 4));

    float d[4][2][4] = {};

    uint4 ahv[2], alv[2]; float4 bv[2];
#pragma unroll
    for (int j = 0; j < 2; j++) {
        ahv[j] = *(const uint4*)aph[j];
        alv[j] = *(const uint4*)apl[j];
        bv[j]  = __ldg((const float4*)bp[j]);
    }

#pragma unroll 1
    for (int c = 0; c < NI / 32; c++) {
        __syncthreads();
#pragma unroll
        for (int j = 0; j < 2; j++) {
            sts128(smb + AH + sa[j], ahv[j]);
            sts128(smb + AL + sa[j], alv[j]);
            uint32_t h0, h1, l0, l1;
            split4(bv[j], h0, h1, l0, l1);
            sts64(smb + BH + sb[j], h0, h1);
            sts64(smb + BL + sb[j], l0, l1);
        }
        __syncthreads();
        if (c + 1 < NI / 32) {
#pragma unroll
            for (int j = 0; j < 2; j++) {
                aph[j] += 32; apl[j] += 32; bp[j] += 32;
                ahv[j] = *(const uint4*)aph[j];
                alv[j] = *(const uint4*)apl[j];
                bv[j]  = __ldg((const float4*)bp[j]);
            }
        }
#pragma unroll
        for (int s = 0; s < 2; s++) {
            uint32_t Ah[4][4], Al[4][4];
#pragma unroll
            for (int mt = 0; mt < 4; mt++) {
                ldm_x4(smb + AH + a_off + mt * 16 * RS + s * 32, Ah[mt]);
                ldm_x4(smb + AL + a_off + mt * 16 * RS + s * 32, Al[mt]);
            }
            uint32_t qh[4], ql[4];
            ldm_x4(smb + BH + b_off + s * 32, qh);
            ldm_x4(smb + BL + b_off + s * 32, ql);
#pragma unroll
            for (int mt = 0; mt < 4; mt++)
#pragma unroll
                for (int nt = 0; nt < 2; nt++) {
                    mma16816(d[mt][nt], Ah[mt], qh[nt * 2], qh[nt * 2 + 1]);
                    mma16816(d[mt][nt], Ah[mt], ql[nt * 2], ql[nt * 2 + 1]);
                    mma16816(d[mt][nt], Al[mt], qh[nt * 2], qh[nt * 2 + 1]);
                }
        }
    }

    int lr = lane >> 2, lc = lane & 3;
#pragma unroll
    for (int mt = 0; mt < 4; mt++)
#pragma unroll
        for (int p = 0; p < 2; p++) {
            int m = m0 + mt * 16 + lr + p * 8;
            int slot = row0 + m;
            if (slot < n_e) {
                int   t = toks[m];
                float w = wts[m];
                float* dst = out + (size_t)t * NH;
#pragma unroll
                for (int nt = 0; nt < 2; nt++) {
                    int n = col0 + n0 + nt * 8 + lc * 2;
                    atomicAdd(dst + n,     w * d[mt][nt][2 * p]);
                    atomicAdd(dst + n + 1, w * d[mt][nt][2 * p + 1]);
                }
            }
        }
}

// ---------------- launch ----------------
extern "C" void kernel_launch(void* const* d_in, const int* in_sizes, int n_in,
                              void* d_out, int out_size) {
    const float* x  = (const float*)d_in[0];
    const float* gw = (const float*)d_in[1];
    const float* w1 = (const float*)d_in[2];
    const float* w3 = (const float*)d_in[3];
    const float* w2 = (const float*)d_in[4];
    float* out = (float*)d_out;

    cudaMemsetAsync(out, 0, (size_t)out_size * sizeof(float), 0);
    zero_counts_kernel<<<1, 32>>>();
    router_kernel<<<(NT * 32 + 255) / 256, 256>>>(x, gw);

    dim3 grid1(NI / 64, NT / 128, NE);
    gemm1_mma<<<grid1, 256>>>(x, w1, w3);

    dim3 grid2(NH / 64, NT / 128, NE);
    gemm2_mma<<<grid2, 256>>>(w2, out);
}

// round 4
// speedup vs baseline: 2.6445x; 1.0342x over previous
#include <cuda_runtime.h>
#include <cuda_bf16.h>
#include <math.h>
#include <stdint.h>

#define NE 8
#define NH 1024
#define NI 2048
#define NT 2048
#define RS 80   // smem row stride (bytes): 20-word stride -> conflict-free ldmatrix

// Scratch (static __device__ — allocation-free per harness rules)
__device__ int   g_count[NE];
__device__ int   g_list[NE * NT];
__device__ float g_wt[NE * NT];
__device__ __nv_bfloat16 g_act_hi[(size_t)NE * NT * NI];
__device__ __nv_bfloat16 g_act_lo[(size_t)NE * NT * NI];

// ---------------- helpers ----------------
__device__ __forceinline__ uint32_t smem_u32(const void* p) {
    uint32_t r;
    asm("{ .reg .u64 t; cvta.to.shared.u64 t, %1; cvt.u32.u64 %0, t; }" : "=r"(r) : "l"(p));
    return r;
}
__device__ __forceinline__ void ldm_x4(uint32_t a, uint32_t r[4]) {
    asm volatile("ldmatrix.sync.aligned.m8n8.x4.shared.b16 {%0,%1,%2,%3}, [%4];"
                 : "=r"(r[0]), "=r"(r[1]), "=r"(r[2]), "=r"(r[3]) : "r"(a));
}
__device__ __forceinline__ void mma16816(float d[4], const uint32_t a[4],
                                         uint32_t b0, uint32_t b1) {
    asm volatile("mma.sync.aligned.m16n8k16.row.col.f32.bf16.bf16.f32 "
                 "{%0,%1,%2,%3}, {%4,%5,%6,%7}, {%8,%9}, {%0,%1,%2,%3};"
                 : "+f"(d[0]), "+f"(d[1]), "+f"(d[2]), "+f"(d[3])
                 : "r"(a[0]), "r"(a[1]), "r"(a[2]), "r"(a[3]), "r"(b0), "r"(b1));
}
__device__ __forceinline__ void sts64(uint32_t a, uint32_t x, uint32_t y) {
    asm volatile("st.shared.v2.b32 [%0], {%1,%2};" :: "r"(a), "r"(x), "r"(y) : "memory");
}
__device__ __forceinline__ uint32_t pk2(float a, float b) {
    __nv_bfloat162 t = __floats2bfloat162_rn(a, b);
    return *reinterpret_cast<uint32_t*>(&t);
}
__device__ __forceinline__ void split4(float4 v, uint32_t& h0, uint32_t& h1,
                                       uint32_t& l0, uint32_t& l1) {
    float hx = __bfloat162float(__float2bfloat16_rn(v.x));
    float hy = __bfloat162float(__float2bfloat16_rn(v.y));
    float hz = __bfloat162float(__float2bfloat16_rn(v.z));
    float hw = __bfloat162float(__float2bfloat16_rn(v.w));
    h0 = pk2(hx, hy); h1 = pk2(hz, hw);
    l0 = pk2(v.x - hx, v.y - hy); l1 = pk2(v.z - hz, v.w - hw);
}
__device__ __forceinline__ void cp_async16(uint32_t dst, const void* src, int srcbytes) {
    asm volatile("cp.async.cg.shared.global [%0], [%1], 16, %2;"
                 :: "r"(dst), "l"(src), "r"(srcbytes) : "memory");
}
#define CP_COMMIT() asm volatile("cp.async.commit_group;" ::: "memory")
#define CP_WAIT0()  asm volatile("cp.async.wait_group 0;" ::: "memory")

// ---------------- router ----------------
__global__ void zero_counts_kernel() {
    if (threadIdx.x < NE) g_count[threadIdx.x] = 0;
}

__global__ __launch_bounds__(256) void router_kernel(const float* __restrict__ x,
                                                     const float* __restrict__ gw) {
    int warp = (blockIdx.x * blockDim.x + threadIdx.x) >> 5;
    int lane = threadIdx.x & 31;
    if (warp >= NT) return;
    const float* xr = x + (size_t)warp * NH;
    float xv[32];
#pragma unroll
    for (int j = 0; j < 32; j++) xv[j] = xr[j * 32 + lane];
    float logits[NE];
#pragma unroll
    for (int e = 0; e < NE; e++) {
        const float* g = gw + e * NH;
        float p = 0.f;
#pragma unroll
        for (int j = 0; j < 32; j++) p += xv[j] * g[j * 32 + lane];
#pragma unroll
        for (int o = 16; o > 0; o >>= 1) p += __shfl_xor_sync(0xffffffffu, p, o);
        logits[e] = p;
    }
    if (lane == 0) {
        int i1 = 0;
#pragma unroll
        for (int e = 1; e < NE; e++) if (logits[e] > logits[i1]) i1 = e;
        int i2 = (i1 == 0) ? 1 : 0;
#pragma unroll
        for (int e = 0; e < NE; e++) if (e != i1 && logits[e] > logits[i2]) i2 = e;
        float s2  = __expf(logits[i2] - logits[i1]);
        float inv = 1.f / (1.f + s2);
        int p0 = atomicAdd(&g_count[i1], 1);
        g_list[i1 * NT + p0] = warp;
        g_wt [i1 * NT + p0] = inv;
        int p1 = atomicAdd(&g_count[i2], 1);
        g_list[i2 * NT + p1] = warp;
        g_wt [i2 * NT + p1] = s2 * inv;
    }
}

// ---------------- GEMM1: act = silu(x*w1^T) * (x*w3^T) ----------------
// CTA 128(M) x 64(N=i), K-chunk 32, double-buffered. 8 warps 4(M)x2(N), warp 32x32.
// Stage layout (bytes, per stage 40960): AH 0, AL 10240, B1H 20480, B1L 25600, B3H 30720, B3L 35840
#define G1_STG 40960
__global__ __launch_bounds__(256) void gemm1_mma(const float* __restrict__ x,
                                                 const float* __restrict__ w1,
                                                 const float* __restrict__ w3) {
    int e   = blockIdx.z;
    int n_e = g_count[e];
    int row0 = blockIdx.y * 128;
    if (row0 >= n_e) return;
    int col0 = blockIdx.x * 64;

    extern __shared__ __align__(128) char sm[];
    int* toks = (int*)sm;
    int tid = threadIdx.x, wid = tid >> 5, lane = tid & 31;
    if (tid < 128) toks[tid] = (row0 + tid < n_e) ? g_list[e * NT + row0 + tid] : -1;
    __syncthreads();
    uint32_t smb = smem_u32(sm);

    // per-thread global load slots
    const float* ap[4]; bool avld[4]; uint32_t sa[4];
#pragma unroll
    for (int j = 0; j < 4; j++) {
        int idx = j * 256 + tid, r = idx >> 3, c4 = idx & 7;
        int t = toks[r];
        avld[j] = t >= 0;
        ap[j] = x + (size_t)(t < 0 ? 0 : t) * NH + c4 * 4;
        sa[j] = (uint32_t)(r * RS + c4 * 8);
    }
    const float *bp1[2], *bp3[2]; uint32_t sb[2];
#pragma unroll
    for (int j = 0; j < 2; j++) {
        int idx = j * 256 + tid, r = idx >> 3, c4 = idx & 7;
        size_t off = (size_t)e * NI * NH + (size_t)(col0 + r) * NH + c4 * 4;
        bp1[j] = w1 + off;
        bp3[j] = w3 + off;
        sb[j] = (uint32_t)(r * RS + c4 * 8);
    }

    int m0 = (wid & 3) * 32, n0 = (wid >> 2) * 32;
    uint32_t a_off = (uint32_t)((m0 + (lane & 15)) * RS + ((lane >> 4) << 4));
    uint32_t b_off = (uint32_t)((n0 + (lane & 7) + ((lane >> 4) << 3)) * RS +
                                (((lane >> 3) & 1) << 4));

    float dg[2][4][4] = {}, du[2][4][4] = {};
    float4 av[4], b1v[2], b3v[2];

    // prologue: chunk0 -> regs -> stage0; chunk1 -> regs
#pragma unroll
    for (int j = 0; j < 4; j++)
        av[j] = avld[j] ? __ldg((const float4*)ap[j]) : make_float4(0.f, 0.f, 0.f, 0.f);
#pragma unroll
    for (int j = 0; j < 2; j++) { b1v[j] = __ldg((const float4*)bp1[j]); b3v[j] = __ldg((const float4*)bp3[j]); }
    {
        uint32_t s0 = smb + 1024, h0, h1, l0, l1;
#pragma unroll
        for (int j = 0; j < 4; j++) {
            split4(av[j], h0, h1, l0, l1);
            sts64(s0 + sa[j], h0, h1);
            sts64(s0 + 10240 + sa[j], l0, l1);
        }
#pragma unroll
        for (int j = 0; j < 2; j++) {
            split4(b1v[j], h0, h1, l0, l1);
            sts64(s0 + 20480 + sb[j], h0, h1);
            sts64(s0 + 25600 + sb[j], l0, l1);
            split4(b3v[j], h0, h1, l0, l1);
            sts64(s0 + 30720 + sb[j], h0, h1);
            sts64(s0 + 35840 + sb[j], l0, l1);
        }
    }
#pragma unroll
    for (int j = 0; j < 4; j++)
        av[j] = avld[j] ? __ldg((const float4*)(ap[j] + 32)) : make_float4(0.f, 0.f, 0.f, 0.f);
#pragma unroll
    for (int j = 0; j < 2; j++) { b1v[j] = __ldg((const float4*)(bp1[j] + 32)); b3v[j] = __ldg((const float4*)(bp3[j] + 32)); }
    __syncthreads();

    const int NC = NH / 32;
#pragma unroll 1
    for (int c = 0; c < NC; c++) {
        int s = c & 1;
        uint32_t cur = smb + 1024 + s * G1_STG;
        uint32_t nxt = smb + 1024 + (s ^ 1) * G1_STG;
        if (c + 1 < NC) {
            uint32_t h0, h1, l0, l1;
#pragma unroll
            for (int j = 0; j < 4; j++) {
                split4(av[j], h0, h1, l0, l1);
                sts64(nxt + sa[j], h0, h1);
                sts64(nxt + 10240 + sa[j], l0, l1);
            }
#pragma unroll
            for (int j = 0; j < 2; j++) {
                split4(b1v[j], h0, h1, l0, l1);
                sts64(nxt + 20480 + sb[j], h0, h1);
                sts64(nxt + 25600 + sb[j], l0, l1);
                split4(b3v[j], h0, h1, l0, l1);
                sts64(nxt + 30720 + sb[j], h0, h1);
                sts64(nxt + 35840 + sb[j], l0, l1);
            }
        }
        if (c + 2 < NC) {
            int ko = (c + 2) * 32;
#pragma unroll
            for (int j = 0; j < 4; j++)
                av[j] = avld[j] ? __ldg((const float4*)(ap[j] + ko)) : make_float4(0.f, 0.f, 0.f, 0.f);
#pragma unroll
            for (int j = 0; j < 2; j++) {
                b1v[j] = __ldg((const float4*)(bp1[j] + ko));
                b3v[j] = __ldg((const float4*)(bp3[j] + ko));
            }
        }
#pragma unroll
        for (int s2 = 0; s2 < 2; s2++) {
            uint32_t Ah[2][4], Al[2][4];
#pragma unroll
            for (int mt = 0; mt < 2; mt++) {
                ldm_x4(cur + a_off + mt * 16 * RS + s2 * 32, Ah[mt]);
                ldm_x4(cur + 10240 + a_off + mt * 16 * RS + s2 * 32, Al[mt]);
            }
            uint32_t B1h[2][4], B1l[2][4], B3h[2][4], B3l[2][4];
#pragma unroll
            for (int j = 0; j < 2; j++) {
                ldm_x4(cur + 20480 + b_off + j * 16 * RS + s2 * 32, B1h[j]);
                ldm_x4(cur + 25600 + b_off + j * 16 * RS + s2 * 32, B1l[j]);
                ldm_x4(cur + 30720 + b_off + j * 16 * RS + s2 * 32, B3h[j]);
                ldm_x4(cur + 35840 + b_off + j * 16 * RS + s2 * 32, B3l[j]);
            }
#pragma unroll
            for (int mt = 0; mt < 2; mt++)
#pragma unroll
                for (int nt = 0; nt < 4; nt++) {
                    int j = nt >> 1, o = (nt & 1) * 2;
                    mma16816(dg[mt][nt], Ah[mt], B1h[j][o], B1h[j][o + 1]);
                    mma16816(dg[mt][nt], Ah[mt], B1l[j][o], B1l[j][o + 1]);
                    mma16816(dg[mt][nt], Al[mt], B1h[j][o], B1h[j][o + 1]);
                    mma16816(du[mt][nt], Ah[mt], B3h[j][o], B3h[j][o + 1]);
                    mma16816(du[mt][nt], Ah[mt], B3l[j][o], B3l[j][o + 1]);
                    mma16816(du[mt][nt], Al[mt], B3h[j][o], B3h[j][o + 1]);
                }
        }
        __syncthreads();
    }

    // epilogue: silu(g)*u, split to bf16 hi/lo
    int lr = lane >> 2, lc = lane & 3;
#pragma unroll
    for (int mt = 0; mt < 2; mt++)
#pragma unroll
        for (int p = 0; p < 2; p++) {
            int m = m0 + mt * 16 + lr + p * 8;
            int slot = row0 + m;
            if (slot < n_e) {
#pragma unroll
                for (int nt = 0; nt < 4; nt++) {
                    int n = col0 + n0 + nt * 8 + lc * 2;
                    float g0 = dg[mt][nt][2 * p], g1 = dg[mt][nt][2 * p + 1];
                    float u0 = du[mt][nt][2 * p], u1 = du[mt][nt][2 * p + 1];
                    float a0 = u0 * g0 / (1.f + __expf(-g0));
                    float a1 = u1 * g1 / (1.f + __expf(-g1));
                    __nv_bfloat16 h0 = __float2bfloat16_rn(a0);
                    __nv_bfloat16 h1 = __float2bfloat16_rn(a1);
                    __nv_bfloat162 hp; hp.x = h0; hp.y = h1;
                    size_t o = ((size_t)e * NT + slot) * NI + n;
                    *(uint32_t*)(g_act_hi + o) = *reinterpret_cast<uint32_t*>(&hp);
                    *(uint32_t*)(g_act_lo + o) =
                        pk2(a0 - __bfloat162float(h0), a1 - __bfloat162float(h1));
                }
            }
        }
}

// ---------------- GEMM2: out += route_w * (act * w2^T) ----------------
// CTA 128(M) x 128(N=h), K-chunk 32, double-buffered. 8 warps 4(M)x2(N), warp 32x64.
// Stage layout (per stage 40960): AH 0, AL 10240, BH 20480, BL 30720
#define G2_STG 40960
__global__ __launch_bounds__(256) void gemm2_mma(const float* __restrict__ w2,
                                                 float* __restrict__ out) {
    int e   = blockIdx.z;
    int n_e = g_count[e];
    int row0 = blockIdx.y * 128;
    if (row0 >= n_e) return;
    int col0 = blockIdx.x * 128;

    extern __shared__ __align__(128) char sm[];
    int*   toks = (int*)sm;
    float* wts  = (float*)(sm + 512);
    int tid = threadIdx.x, wid = tid >> 5, lane = tid & 31;
    if (tid < 128) {
        int slot = row0 + tid;
        toks[tid] = (slot < n_e) ? g_list[e * NT + slot] : 0;
        wts[tid]  = (slot < n_e) ? g_wt [e * NT + slot] : 0.f;
    }
    __syncthreads();
    uint32_t smb = smem_u32(sm);

    // A via cp.async (act already bf16 hi/lo in gmem)
    const __nv_bfloat16* asrc[4]; int asz[4]; uint32_t adst[4];
#pragma unroll
    for (int j = 0; j < 4; j++) {
        int idx = j * 256 + tid, r = idx >> 2, c16 = idx & 3;
        int rr = r & 127;
        bool hi = r < 128;
        int slot = row0 + rr;
        bool v = slot < n_e;
        const __nv_bfloat16* base = hi ? g_act_hi : g_act_lo;
        asrc[j] = base + ((size_t)e * NT + (v ? slot : 0)) * NI + c16 * 8;
        asz[j]  = v ? 16 : 0;
        adst[j] = (hi ? 0u : 10240u) + (uint32_t)(rr * RS + c16 * 16);
    }
    // B (w2 fp32, split in regs)
    const float* bp[4]; uint32_t sb[4];
#pragma unroll
    for (int j = 0; j < 4; j++) {
        int idx = j * 256 + tid, r = idx >> 3, c4 = idx & 7;
        bp[j] = w2 + (size_t)e * NH * NI + (size_t)(col0 + r) * NI + c4 * 4;
        sb[j] = (uint32_t)(r * RS + c4 * 8);
    }

    int m0 = (wid & 3) * 32, n0 = (wid >> 2) * 64;
    uint32_t a_off = (uint32_t)((m0 + (lane & 15)) * RS + ((lane >> 4) << 4));
    uint32_t b_off = (uint32_t)((n0 + (lane & 7) + ((lane >> 4) << 3)) * RS +
                                (((lane >> 3) & 1) << 4));

    float d[2][8][4] = {};
    float4 bv[4];

    // prologue
    {
        uint32_t s0 = smb + 1024;
#pragma unroll
        for (int j = 0; j < 4; j++) cp_async16(s0 + adst[j], asrc[j], asz[j]);
        CP_COMMIT();
#pragma unroll
        for (int j = 0; j < 4; j++) bv[j] = __ldg((const float4*)bp[j]);
        uint32_t h0, h1, l0, l1;
#pragma unroll
        for (int j = 0; j < 4; j++) {
            split4(bv[j], h0, h1, l0, l1);
            sts64(s0 + 20480 + sb[j], h0, h1);
            sts64(s0 + 30720 + sb[j], l0, l1);
        }
#pragma unroll
        for (int j = 0; j < 4; j++) bv[j] = __ldg((const float4*)(bp[j] + 32));
        CP_WAIT0();
    }
    __syncthreads();

    const int NC = NI / 32;
#pragma unroll 1
    for (int c = 0; c < NC; c++) {
        int s = c & 1;
        uint32_t cur = smb + 1024 + s * G2_STG;
        uint32_t nxt = smb + 1024 + (s ^ 1) * G2_STG;
        if (c + 1 < NC) {
            int ko = (c + 1) * 32;
#pragma unroll
            for (int j = 0; j < 4; j++) cp_async16(nxt + adst[j], asrc[j] + ko, asz[j]);
            CP_COMMIT();
            uint32_t h0, h1, l0, l1;
#pragma unroll
            for (int j = 0; j < 4; j++) {
                split4(bv[j], h0, h1, l0, l1);
                sts64(nxt + 20480 + sb[j], h0, h1);
                sts64(nxt + 30720 + sb[j], l0, l1);
            }
        }
        if (c + 2 < NC) {
            int ko = (c + 2) * 32;
#pragma unroll
            for (int j = 0; j < 4; j++) bv[j] = __ldg((const float4*)(bp[j] + ko));
        }
#pragma unroll
        for (int s2 = 0; s2 < 2; s2++) {
            uint32_t Ah[2][4], Al[2][4];
#pragma unroll
            for (int mt = 0; mt < 2; mt++) {
                ldm_x4(cur + a_off + mt * 16 * RS + s2 * 32, Ah[mt]);
                ldm_x4(cur + 10240 + a_off + mt * 16 * RS + s2 * 32, Al[mt]);
            }
            uint32_t Bh[4][4], Bl[4][4];
#pragma unroll
            for (int j = 0; j < 4; j++) {
                ldm_x4(cur + 20480 + b_off + j * 16 * RS + s2 * 32, Bh[j]);
                ldm_x4(cur + 30720 + b_off + j * 16 * RS + s2 * 32, Bl[j]);
            }
#pragma unroll
            for (int mt = 0; mt < 2; mt++)
#pragma unroll
                for (int nt = 0; nt < 8; nt++) {
                    int j = nt >> 1, o = (nt & 1) * 2;
                    mma16816(d[mt][nt], Ah[mt], Bh[j][o], Bh[j][o + 1]);
                    mma16816(d[mt][nt], Ah[mt], Bl[j][o], Bl[j][o + 1]);
                    mma16816(d[mt][nt], Al[mt], Bh[j][o], Bh[j][o + 1]);
                }
        }
        if (c + 1 < NC) CP_WAIT0();
        __syncthreads();
    }

    int lr = lane >> 2, lc = lane & 3;
#pragma unroll
    for (int mt = 0; mt < 2; mt++)
#pragma unroll
        for (int p = 0; p < 2; p++) {
            int m = m0 + mt * 16 + lr + p * 8;
            int slot = row0 + m;
            if (slot < n_e) {
                int   t = toks[m];
                float w = wts[m];
                float* dst = out + (size_t)t * NH;
#pragma unroll
                for (int nt = 0; nt < 8; nt++) {
                    int n = col0 + n0 + nt * 8 + lc * 2;
                    atomicAdd(dst + n,     w * d[mt][nt][2 * p]);
                    atomicAdd(dst + n + 1, w * d[mt][nt][2 * p + 1]);
                }
            }
        }
}

// ---------------- launch ----------------
extern "C" void kernel_launch(void* const* d_in, const int* in_sizes, int n_in,
                              void* d_out, int out_size) {
    const float* x  = (const float*)d_in[0];
    const float* gw = (const float*)d_in[1];
    const float* w1 = (const float*)d_in[2];
    const float* w3 = (const float*)d_in[3];
    const float* w2 = (const float*)d_in[4];
    float* out = (float*)d_out;

    const int SMEM1 = 1024 + 2 * G1_STG;   // 82944
    const int SMEM2 = 1024 + 2 * G2_STG;   // 82944
    cudaFuncSetAttribute(gemm1_mma, cudaFuncAttributeMaxDynamicSharedMemorySize, SMEM1);
    cudaFuncSetAttribute(gemm2_mma, cudaFuncAttributeMaxDynamicSharedMemorySize, SMEM2);

    cudaMemsetAsync(out, 0, (size_t)out_size * sizeof(float), 0);
    zero_counts_kernel<<<1, 32>>>();
    router_kernel<<<(NT * 32 + 255) / 256, 256>>>(x, gw);

    dim3 grid1(NI / 64, NT / 128, NE);
    gemm1_mma<<<grid1, 256, SMEM1>>>(x, w1, w3);

    dim3 grid2(NH / 128, NT / 128, NE);
    gemm2_mma<<<grid2, 256, SMEM2>>>(w2, out);
}